// round 1
// baseline (speedup 1.0000x reference)
#include <cuda_runtime.h>
#include <math.h>

#define NTOK 175616   // 56*56*56
#define CDIM 96
#define NW   512
#define WN   343
#define HIDD 384

// -------------------- scratch (device globals; no runtime alloc) -------------
__device__ float g_xw  [NW*WN*CDIM];   // LN1 output, windowed (win, t, c)
__device__ float g_qp  [NW*WN*CDIM];
__device__ float g_kp  [NW*WN*CDIM];
__device__ float g_vp  [NW*WN*CDIM];
__device__ float g_q   [NW*WN*CDIM];
__device__ float g_k   [NW*WN*CDIM];
__device__ float g_v   [NW*WN*CDIM];
__device__ float g_attn[NW*WN*WN];     // softmax probabilities
__device__ float g_ot  [NW*WN*CDIM];   // attention out, stored axis-mixed: flat = c*343 + n
__device__ float g_xres[NTOK*CDIM];    // residual stream (token-major)
__device__ float g_ln2 [NTOK*CDIM];
__device__ float g_h   [NTOK*HIDD];    // MLP hidden

// -------------------- LN1 + roll(-3) + window partition ---------------------
__global__ void k_ln1(const float* __restrict__ x,
                      const float* __restrict__ gg, const float* __restrict__ bb) {
    int warp = (blockIdx.x * blockDim.x + threadIdx.x) >> 5;
    int lane = threadIdx.x & 31;
    if (warp >= NW * WN) return;
    int win = warp / WN, t = warp % WN;
    int ws = win >> 6, hs = (win >> 3) & 7, wd = win & 7;
    int dz = t / 49, r = t % 49, dy = r / 7, dx = r % 7;
    int s = (ws * 7 + dz + 3) % 56;
    int h = (hs * 7 + dy + 3) % 56;
    int w = (wd * 7 + dx + 3) % 56;
    int p = s * 3136 + h * 56 + w;

    float v0 = x[lane * NTOK + p];
    float v1 = x[(lane + 32) * NTOK + p];
    float v2 = x[(lane + 64) * NTOK + p];
    float sum = v0 + v1 + v2;
    float sq  = v0 * v0 + v1 * v1 + v2 * v2;
    #pragma unroll
    for (int o = 16; o; o >>= 1) {
        sum += __shfl_xor_sync(0xffffffffu, sum, o);
        sq  += __shfl_xor_sync(0xffffffffu, sq, o);
    }
    float mean = sum * (1.f / 96.f);
    float var  = sq * (1.f / 96.f) - mean * mean;
    float inv  = rsqrtf(var + 1e-5f);
    int base = warp * CDIM;
    g_xw[base + lane]      = (v0 - mean) * inv * gg[lane]      + bb[lane];
    g_xw[base + lane + 32] = (v1 - mean) * inv * gg[lane + 32] + bb[lane + 32];
    g_xw[base + lane + 64] = (v2 - mean) * inv * gg[lane + 64] + bb[lane + 64];
}

// -------------------- generic tiled GEMM: Out[M,N] = A[M,K] @ W[N,K]^T + b ---
// EPI: 0 = bias   1 = bias+GELU(exact)   2 = bias + residual + transposed store
template<int EPI>
__global__ __launch_bounds__(256)
void k_gemm(const float* __restrict__ A, const float* __restrict__ W,
            const float* __restrict__ bias, float* __restrict__ Out,
            int M, int Nout, int K,
            const float* __restrict__ Res, float* __restrict__ OutT) {
    __shared__ float As[32 * 65];
    __shared__ float Bs[32 * 97];
    int bm = blockIdx.x * 64;
    int bn = blockIdx.y * 96;
    int tid = threadIdx.x;
    int tx = tid & 15, ty = tid >> 4;
    float acc[4][6] = {};

    for (int k0 = 0; k0 < K; k0 += 32) {
        #pragma unroll
        for (int l = 0; l < 8; l++) {
            int e = tid + l * 256;
            int rr = e >> 5, kk = e & 31;
            As[kk * 65 + rr] = A[(bm + rr) * K + k0 + kk];
        }
        #pragma unroll
        for (int l = 0; l < 12; l++) {
            int e = tid + l * 256;
            int col = e >> 5, kk = e & 31;
            Bs[kk * 97 + col] = W[(bn + col) * K + k0 + kk];
        }
        __syncthreads();
        #pragma unroll
        for (int kk = 0; kk < 32; kk++) {
            float a[4], b[6];
            #pragma unroll
            for (int i = 0; i < 4; i++) a[i] = As[kk * 65 + ty * 4 + i];
            #pragma unroll
            for (int j = 0; j < 6; j++) b[j] = Bs[kk * 97 + tx * 6 + j];
            #pragma unroll
            for (int i = 0; i < 4; i++)
                #pragma unroll
                for (int j = 0; j < 6; j++)
                    acc[i][j] += a[i] * b[j];
        }
        __syncthreads();
    }

    #pragma unroll
    for (int i = 0; i < 4; i++) {
        int row = bm + ty * 4 + i;
        #pragma unroll
        for (int j = 0; j < 6; j++) {
            int col = bn + tx * 6 + j;
            float v = acc[i][j] + bias[col];
            if (EPI == 1) {
                v = 0.5f * v * (1.f + erff(v * 0.70710678118654752f));
                Out[row * Nout + col] = v;
            } else if (EPI == 2) {
                v += Res[row * CDIM + col];
                OutT[col * NTOK + row] = v;
            } else {
                Out[row * Nout + col] = v;
            }
        }
    }
}

// -------------------- depthwise 3x3x3 within each 7x7x7 window --------------
__global__ __launch_bounds__(352)
void k_dw(const float* __restrict__ In, const float* __restrict__ Wt,
          const float* __restrict__ Bi, float* __restrict__ Ot) {
    extern __shared__ float sm[];
    float* sin_ = sm;                 // 343 * 100
    float* wsm  = sm + 343 * 100;     // transposed: [k*96 + c]
    int win = blockIdx.x;
    int tid = threadIdx.x;
    const float* inw = In + win * WN * CDIM;
    for (int e = tid; e < WN * CDIM; e += blockDim.x)
        sin_[(e / 96) * 100 + (e % 96)] = inw[e];
    for (int e = tid; e < 96 * 27; e += blockDim.x) {
        int c = e / 27, k = e % 27;
        wsm[k * 96 + c] = Wt[e];
    }
    __syncthreads();
    if (tid >= WN) return;
    int t = tid;
    int dz = t / 49, r = t % 49, dy = r / 7, dx = r % 7;
    int  tn[27];
    bool val[27];
    #pragma unroll
    for (int k = 0; k < 27; k++) {
        int kd = k / 9, kh = (k / 3) % 3, kw = k % 3;
        int nz = dz + kd - 1, ny = dy + kh - 1, nx = dx + kw - 1;
        bool ok = (unsigned)nz < 7u && (unsigned)ny < 7u && (unsigned)nx < 7u;
        val[k] = ok;
        tn[k]  = ok ? (nz * 49 + ny * 7 + nx) : 0;
    }
    float* outw = Ot + win * WN * CDIM + t * CDIM;
    for (int c4 = 0; c4 < 96; c4 += 4) {
        float4 a = *(const float4*)(Bi + c4);
        #pragma unroll
        for (int k = 0; k < 27; k++) {
            if (val[k]) {
                float4 iv = *(const float4*)(sin_ + tn[k] * 100 + c4);
                float4 wv = *(const float4*)(wsm + k * 96 + c4);
                a.x += iv.x * wv.x; a.y += iv.y * wv.y;
                a.z += iv.z * wv.z; a.w += iv.w * wv.w;
            }
        }
        *(float4*)(outw + c4) = a;
    }
}

// -------------------- attention: scores + shift-mask + softmax --------------
__global__ __launch_bounds__(256)
void k_att1(const float* __restrict__ Q, const float* __restrict__ Km) {
    extern __shared__ float sm[];
    float* ks = sm;              // 343 * 100
    float* qs = sm + 343 * 100;  // 8 warps * 100
    int win = blockIdx.x;
    int tid = threadIdx.x, lane = tid & 31, wp = tid >> 5;
    const float* kw = Km + win * WN * CDIM;
    for (int e = tid; e < WN * CDIM; e += 256)
        ks[(e / 96) * 100 + (e % 96)] = kw[e];
    __syncthreads();

    int ws = win >> 6, hs = (win >> 3) & 7, wd = win & 7;
    bool bz = (ws == 7), bh = (hs == 7), bw = (wd == 7);
    const float* qw = Q + win * WN * CDIM;
    const float scale = 0.10206207261596575f; // 1/sqrt(96)
    float* myq = qs + wp * 100;

    for (int q = wp; q < WN; q += 8) {
        myq[lane]      = qw[q * 96 + lane]      * scale;
        myq[lane + 32] = qw[q * 96 + lane + 32] * scale;
        myq[lane + 64] = qw[q * 96 + lane + 64] * scale;
        __syncwarp();
        int dzq = q / 49, rq = q % 49, dyq = rq / 7, dxq = rq % 7;
        bool gzq = dzq < 4, ghq = dyq < 4, gwq = dxq < 4;

        float sreg[11];
        #pragma unroll
        for (int j = 0; j < 11; j++) {
            int m = lane + 32 * j;
            if (m < WN) {
                float acc = 0.f;
                const float* krow = ks + m * 100;
                #pragma unroll
                for (int c4 = 0; c4 < 96; c4 += 4) {
                    float4 kv = *(const float4*)(krow + c4);
                    float4 qv = *(const float4*)(myq + c4);
                    acc += kv.x * qv.x + kv.y * qv.y + kv.z * qv.z + kv.w * qv.w;
                }
                int dzm = m / 49, rm = m % 49, dym = rm / 7, dxm = rm % 7;
                bool same = (!bz || (gzq == (dzm < 4))) &&
                            (!bh || (ghq == (dym < 4))) &&
                            (!bw || (gwq == (dxm < 4)));
                if (!same) acc -= 100.f;
                sreg[j] = acc;
            } else sreg[j] = -1e30f;
        }
        float mx = -1e30f;
        #pragma unroll
        for (int j = 0; j < 11; j++) mx = fmaxf(mx, sreg[j]);
        #pragma unroll
        for (int o = 16; o; o >>= 1) mx = fmaxf(mx, __shfl_xor_sync(0xffffffffu, mx, o));
        float sum = 0.f;
        #pragma unroll
        for (int j = 0; j < 11; j++) { sreg[j] = __expf(sreg[j] - mx); sum += sreg[j]; }
        #pragma unroll
        for (int o = 16; o; o >>= 1) sum += __shfl_xor_sync(0xffffffffu, sum, o);
        float rinv = 1.f / sum;
        float* arow = g_attn + (win * WN + q) * WN;
        #pragma unroll
        for (int j = 0; j < 11; j++) {
            int m = lane + 32 * j;
            if (m < WN) arow[m] = sreg[j] * rinv;
        }
        __syncwarp();
    }
}

// -------------------- attention: P @ V, store axis-mixed (c*343 + n) --------
__global__ __launch_bounds__(256)
void k_att2(const float* __restrict__ V) {
    extern __shared__ float sm[];
    float* vs = sm;              // 343 * 100
    float* ps = sm + 343 * 100;  // 8 warps * 4 * 344
    int win = blockIdx.x;
    int tid = threadIdx.x, lane = tid & 31, wp = tid >> 5;
    const float* vw = V + win * WN * CDIM;
    for (int e = tid; e < WN * CDIM; e += 256)
        vs[(e / 96) * 100 + (e % 96)] = vw[e];
    __syncthreads();

    float* myp = ps + wp * 4 * 344;
    float* ob  = g_ot + win * WN * CDIM;

    for (int g = wp; g < 86; g += 8) {           // 86*4 = 344 >= 343
        int q0 = g * 4;
        int nq = WN - q0; if (nq > 4) nq = 4;
        #pragma unroll
        for (int qi = 0; qi < 4; qi++) {
            float* prow = myp + qi * 344;
            if (qi < nq) {
                const float* arow = g_attn + (win * WN + q0 + qi) * WN;
                #pragma unroll
                for (int j = 0; j < 11; j++) {
                    int m = lane + 32 * j;
                    if (m < WN) prow[m] = arow[m];
                }
            } else {
                #pragma unroll
                for (int j = 0; j < 11; j++) {
                    int m = lane + 32 * j;
                    if (m < WN) prow[m] = 0.f;
                }
            }
        }
        __syncwarp();
        float acc[4][3] = {};
        for (int m = 0; m < WN; m++) {
            float v0 = vs[m * 100 + lane];
            float v1 = vs[m * 100 + lane + 32];
            float v2 = vs[m * 100 + lane + 64];
            #pragma unroll
            for (int qi = 0; qi < 4; qi++) {
                float pm = myp[qi * 344 + m];
                acc[qi][0] += pm * v0;
                acc[qi][1] += pm * v1;
                acc[qi][2] += pm * v2;
            }
        }
        for (int qi = 0; qi < nq; qi++) {
            ob[ lane       * WN + q0 + qi] = acc[qi][0];
            ob[(lane + 32) * WN + q0 + qi] = acc[qi][1];
            ob[(lane + 64) * WN + q0 + qi] = acc[qi][2];
        }
        __syncwarp();
    }
}

// -------------------- window-reverse + roll(+3) + residual add --------------
__global__ void k_res(const float* __restrict__ x) {
    int idx = blockIdx.x * 256 + threadIdx.x;
    if (idx >= NTOK * CDIM) return;
    int p = idx / 96, c = idx % 96;
    int s = p / 3136, r = p % 3136, h = r / 56, w = r % 56;
    int s2 = (s >= 3) ? s - 3 : s + 53;
    int h2 = (h >= 3) ? h - 3 : h + 53;
    int w2 = (w >= 3) ? w - 3 : w + 53;
    int win = (s2 / 7) * 64 + (h2 / 7) * 8 + (w2 / 7);
    int np  = (s2 % 7) * 49 + (h2 % 7) * 7 + (w2 % 7);
    // out2[n',c'] == ot_flat[n'*96 + c']  (the faithful axis-mixing transpose)
    float v = g_ot[win * WN * CDIM + np * 96 + c];
    g_xres[idx] = x[c * NTOK + p] + v;
}

// -------------------- LN2 (token-major) --------------------------------------
__global__ void k_ln2(const float* __restrict__ gg, const float* __restrict__ bb) {
    int warp = (blockIdx.x * blockDim.x + threadIdx.x) >> 5;
    int lane = threadIdx.x & 31;
    if (warp >= NTOK) return;
    const float* xr = g_xres + warp * CDIM;
    float v0 = xr[lane], v1 = xr[lane + 32], v2 = xr[lane + 64];
    float sum = v0 + v1 + v2;
    float sq  = v0 * v0 + v1 * v1 + v2 * v2;
    #pragma unroll
    for (int o = 16; o; o >>= 1) {
        sum += __shfl_xor_sync(0xffffffffu, sum, o);
        sq  += __shfl_xor_sync(0xffffffffu, sq, o);
    }
    float mean = sum * (1.f / 96.f);
    float var  = sq * (1.f / 96.f) - mean * mean;
    float inv  = rsqrtf(var + 1e-5f);
    float* yo = g_ln2 + warp * CDIM;
    yo[lane]      = (v0 - mean) * inv * gg[lane]      + bb[lane];
    yo[lane + 32] = (v1 - mean) * inv * gg[lane + 32] + bb[lane + 32];
    yo[lane + 64] = (v2 - mean) * inv * gg[lane + 64] + bb[lane + 64];
}

// -------------------- launch ---------------------------------------------------
extern "C" void kernel_launch(void* const* d_in, const int* in_sizes, int n_in,
                              void* d_out, int out_size) {
    const float* x   = (const float*)d_in[0];
    const float* n1g = (const float*)d_in[1];
    const float* n1b = (const float*)d_in[2];
    const float* wq  = (const float*)d_in[3];
    const float* bq  = (const float*)d_in[4];
    const float* wk  = (const float*)d_in[5];
    const float* bk  = (const float*)d_in[6];
    const float* wv  = (const float*)d_in[7];
    const float* bv  = (const float*)d_in[8];
    const float* dqw = (const float*)d_in[9];
    const float* dqb = (const float*)d_in[10];
    const float* dkw = (const float*)d_in[11];
    const float* dkb = (const float*)d_in[12];
    const float* dvw = (const float*)d_in[13];
    const float* dvb = (const float*)d_in[14];
    const float* n2g = (const float*)d_in[15];
    const float* n2b = (const float*)d_in[16];
    const float* f1w = (const float*)d_in[17];
    const float* f1b = (const float*)d_in[18];
    const float* f2w = (const float*)d_in[19];
    const float* f2b = (const float*)d_in[20];
    float* out = (float*)d_out;

    float *pxw, *pqp, *pkp, *pvp, *pq, *pk, *pv, *pln2, *ph, *pxres;
    cudaGetSymbolAddress((void**)&pxw,   g_xw);
    cudaGetSymbolAddress((void**)&pqp,   g_qp);
    cudaGetSymbolAddress((void**)&pkp,   g_kp);
    cudaGetSymbolAddress((void**)&pvp,   g_vp);
    cudaGetSymbolAddress((void**)&pq,    g_q);
    cudaGetSymbolAddress((void**)&pk,    g_k);
    cudaGetSymbolAddress((void**)&pv,    g_v);
    cudaGetSymbolAddress((void**)&pln2,  g_ln2);
    cudaGetSymbolAddress((void**)&ph,    g_h);
    cudaGetSymbolAddress((void**)&pxres, g_xres);

    const int DW_SMEM   = (343 * 100 + 27 * 96) * 4;
    const int ATT1_SMEM = (343 * 100 + 8 * 100) * 4;
    const int ATT2_SMEM = (343 * 100 + 8 * 4 * 344) * 4;
    cudaFuncSetAttribute(k_dw,   cudaFuncAttributeMaxDynamicSharedMemorySize, DW_SMEM);
    cudaFuncSetAttribute(k_att1, cudaFuncAttributeMaxDynamicSharedMemorySize, ATT1_SMEM);
    cudaFuncSetAttribute(k_att2, cudaFuncAttributeMaxDynamicSharedMemorySize, ATT2_SMEM);

    // 1) LN1 + roll + window gather
    k_ln1<<<NW * WN / 8, 256>>>(x, n1g, n1b);

    // 2) conv1x1 for q, k, v
    dim3 g1(NTOK / 64, 1);
    k_gemm<0><<<g1, 256>>>(pxw, wq, bq, pqp, NTOK, 96, 96, nullptr, nullptr);
    k_gemm<0><<<g1, 256>>>(pxw, wk, bk, pkp, NTOK, 96, 96, nullptr, nullptr);
    k_gemm<0><<<g1, 256>>>(pxw, wv, bv, pvp, NTOK, 96, 96, nullptr, nullptr);

    // 3) depthwise 3x3x3 per window
    k_dw<<<NW, 352, DW_SMEM>>>(pqp, dqw, dqb, pq);
    k_dw<<<NW, 352, DW_SMEM>>>(pkp, dkw, dkb, pk);
    k_dw<<<NW, 352, DW_SMEM>>>(pvp, dvw, dvb, pv);

    // 4) attention
    k_att1<<<NW, 256, ATT1_SMEM>>>(pq, pk);
    k_att2<<<NW, 256, ATT2_SMEM>>>(pv);

    // 5) reverse + roll back + residual
    k_res<<<(NTOK * CDIM + 255) / 256, 256>>>(x);

    // 6) LN2
    k_ln2<<<NTOK / 8, 256>>>(n2g, n2b);

    // 7) MLP
    dim3 g2(NTOK / 64, HIDD / 96);
    k_gemm<1><<<g2, 256>>>(pln2, f1w, f1b, ph, NTOK, HIDD, 96, nullptr, nullptr);
    dim3 g3(NTOK / 64, 1);
    k_gemm<2><<<g3, 256>>>(ph, f2w, f2b, nullptr, NTOK, 96, HIDD, pxres, out);
}

// round 2
// speedup vs baseline: 1.3562x; 1.3562x over previous
#include <cuda_runtime.h>
#include <math.h>

#define NTOK 175616   // 56*56*56
#define CDIM 96
#define NW   512
#define WN   343
#define HIDD 384

// -------------------- scratch (device globals) -------------------------------
__device__ float g_xw  [NW*WN*CDIM];   // LN1 output, windowed (win, t, c)
__device__ float g_qp  [NW*WN*CDIM];
__device__ float g_kp  [NW*WN*CDIM];
__device__ float g_vp  [NW*WN*CDIM];
__device__ float g_q   [NW*WN*CDIM];
__device__ float g_k   [NW*WN*CDIM];
__device__ float g_v   [NW*WN*CDIM];
__device__ float g_attn[(size_t)NW*WN*WN]; // softmax probabilities
__device__ float g_ot  [NW*WN*CDIM];   // attention out, axis-mixed: flat = c*343 + n
__device__ float g_xres[NTOK*CDIM];    // residual stream (token-major)
__device__ float g_ln2 [NTOK*CDIM];
__device__ float g_h   [NTOK*HIDD];    // MLP hidden
__device__ float g_wqkv[3*CDIM*CDIM];
__device__ float g_bqkv[3*CDIM];

// -------------------- pack qkv weights ---------------------------------------
__global__ void k_prep(const float* __restrict__ wq, const float* __restrict__ bq,
                       const float* __restrict__ wk, const float* __restrict__ bk,
                       const float* __restrict__ wv, const float* __restrict__ bv) {
    int i = blockIdx.x * 256 + threadIdx.x;
    if (i < 3*CDIM*CDIM) {
        int t = i / (CDIM*CDIM), r = i % (CDIM*CDIM);
        g_wqkv[i] = (t == 0) ? wq[r] : (t == 1) ? wk[r] : wv[r];
    }
    if (i < 3*CDIM) {
        int t = i / CDIM, r = i % CDIM;
        g_bqkv[i] = (t == 0) ? bq[r] : (t == 1) ? bk[r] : bv[r];
    }
}

// -------------------- LN1 + roll(-3) + window partition (coalesced) ----------
__global__ __launch_bounds__(256)
void k_ln1(const float* __restrict__ x,
           const float* __restrict__ gg, const float* __restrict__ bb) {
    __shared__ float xs[64*101];
    int p0 = blockIdx.x * 64;
    int tid = threadIdx.x, lane = tid & 31, wp = tid >> 5;
    for (int e = tid; e < 96*64; e += 256) {
        int c = e >> 6, i = e & 63;
        xs[i*101 + c] = x[(size_t)c*NTOK + p0 + i];
    }
    __syncthreads();
    #pragma unroll
    for (int ii = wp; ii < 64; ii += 8) {
        int p = p0 + ii;
        int s = p / 3136, r = p % 3136, h = r / 56, w = r % 56;
        // destination (rolled by -3): a = p - 3 (mod 56) per axis
        int s2 = (s >= 3) ? s - 3 : s + 53;
        int h2 = (h >= 3) ? h - 3 : h + 53;
        int w2 = (w >= 3) ? w - 3 : w + 53;
        int win = (s2/7)*64 + (h2/7)*8 + (w2/7);
        int t   = (s2%7)*49 + (h2%7)*7 + (w2%7);
        float v0 = xs[ii*101 + lane];
        float v1 = xs[ii*101 + lane + 32];
        float v2 = xs[ii*101 + lane + 64];
        float sum = v0 + v1 + v2, sq = v0*v0 + v1*v1 + v2*v2;
        #pragma unroll
        for (int o = 16; o; o >>= 1) {
            sum += __shfl_xor_sync(0xffffffffu, sum, o);
            sq  += __shfl_xor_sync(0xffffffffu, sq, o);
        }
        float mean = sum * (1.f/96.f);
        float var  = sq * (1.f/96.f) - mean*mean;
        float inv  = rsqrtf(var + 1e-5f);
        float* ob = g_xw + ((size_t)win*WN + t)*CDIM;
        ob[lane]      = (v0 - mean)*inv*gg[lane]      + bb[lane];
        ob[lane + 32] = (v1 - mean)*inv*gg[lane + 32] + bb[lane + 32];
        ob[lane + 64] = (v2 - mean)*inv*gg[lane + 64] + bb[lane + 64];
    }
}

// -------------------- tiled GEMM: Out[M,N] = A[M,K] @ W[N,K]^T + b -----------
// EPI: 0 plain, 1 GELU, 2 residual + transposed store, 3 qkv split
template<int EPI>
__global__ __launch_bounds__(256)
void k_gemm(const float* __restrict__ A, const float* __restrict__ W,
            const float* __restrict__ bias, int M, int Nout, int K,
            float* __restrict__ O0, float* __restrict__ O1, float* __restrict__ O2,
            const float* __restrict__ Res, float* __restrict__ OutT) {
    __shared__ float sm[32*132 + 32*98];
    float* As = sm;
    float* Bs = sm + 32*132;
    int bm = blockIdx.x * 128;
    int bn = blockIdx.y * 96;
    int tid = threadIdx.x, tx = tid & 15, ty = tid >> 4;
    int arow = tid >> 3, ak = (tid & 7) * 4;
    float acc[8][6] = {};

    for (int k0 = 0; k0 < K; k0 += 32) {
        #pragma unroll
        for (int l = 0; l < 4; l++) {
            int r = arow + l*32;
            float4 v = *(const float4*)(A + (size_t)(bm + r)*K + k0 + ak);
            As[(ak+0)*132 + r] = v.x;
            As[(ak+1)*132 + r] = v.y;
            As[(ak+2)*132 + r] = v.z;
            As[(ak+3)*132 + r] = v.w;
        }
        #pragma unroll
        for (int l = 0; l < 3; l++) {
            int c = arow + l*32;
            float4 v = *(const float4*)(W + (size_t)(bn + c)*K + k0 + ak);
            Bs[(ak+0)*98 + c] = v.x;
            Bs[(ak+1)*98 + c] = v.y;
            Bs[(ak+2)*98 + c] = v.z;
            Bs[(ak+3)*98 + c] = v.w;
        }
        __syncthreads();
        #pragma unroll
        for (int kk = 0; kk < 32; kk++) {
            float4 a0 = *(const float4*)(As + kk*132 + ty*8);
            float4 a1 = *(const float4*)(As + kk*132 + ty*8 + 4);
            float2 b0 = *(const float2*)(Bs + kk*98 + tx*6);
            float2 b1 = *(const float2*)(Bs + kk*98 + tx*6 + 2);
            float2 b2 = *(const float2*)(Bs + kk*98 + tx*6 + 4);
            float a[8] = {a0.x,a0.y,a0.z,a0.w,a1.x,a1.y,a1.z,a1.w};
            float b[6] = {b0.x,b0.y,b1.x,b1.y,b2.x,b2.y};
            #pragma unroll
            for (int i = 0; i < 8; i++)
                #pragma unroll
                for (int j = 0; j < 6; j++)
                    acc[i][j] += a[i]*b[j];
        }
        __syncthreads();
    }

    if (EPI == 3) {
        float* o = (blockIdx.y == 0) ? O0 : (blockIdx.y == 1) ? O1 : O2;
        #pragma unroll
        for (int i = 0; i < 8; i++) {
            int row = bm + ty*8 + i;
            #pragma unroll
            for (int j = 0; j < 6; j++) {
                int col = tx*6 + j;
                o[(size_t)row*96 + col] = acc[i][j] + bias[bn + col];
            }
        }
    } else if (EPI == 1) {
        #pragma unroll
        for (int i = 0; i < 8; i++) {
            int row = bm + ty*8 + i;
            #pragma unroll
            for (int j = 0; j < 6; j++) {
                int col = bn + tx*6 + j;
                float v = acc[i][j] + bias[col];
                v = 0.5f * v * (1.f + erff(v * 0.70710678118654752f));
                O0[(size_t)row*Nout + col] = v;
            }
        }
    } else if (EPI == 2) {
        // residual add + transposed store via smem staging (48 cols/phase)
        float* st = sm;
        for (int c0 = 0; c0 < 96; c0 += 48) {
            if ((tx < 8) == (c0 == 0)) {
                #pragma unroll
                for (int i = 0; i < 8; i++) {
                    int row = ty*8 + i;
                    #pragma unroll
                    for (int j = 0; j < 6; j++) {
                        int col = tx*6 + j;
                        float v = acc[i][j] + bias[col] + Res[(size_t)(bm + row)*96 + col];
                        st[(col - c0)*132 + row] = v;
                    }
                }
            }
            __syncthreads();
            for (int e = tid; e < 48*128; e += 256) {
                int col = e >> 7, r = e & 127;
                OutT[(size_t)(c0 + col)*NTOK + bm + r] = st[col*132 + r];
            }
            __syncthreads();
        }
    } else {
        #pragma unroll
        for (int i = 0; i < 8; i++) {
            int row = bm + ty*8 + i;
            #pragma unroll
            for (int j = 0; j < 6; j++) {
                int col = bn + tx*6 + j;
                O0[(size_t)row*Nout + col] = acc[i][j] + bias[col];
            }
        }
    }
}

// -------------------- depthwise 3x3x3 within each 7x7x7 window ---------------
__global__ __launch_bounds__(352)
void k_dw(const float* __restrict__ In, const float* __restrict__ Wt,
          const float* __restrict__ Bi, float* __restrict__ Ot) {
    extern __shared__ float sm[];
    float* sin_ = sm;                 // 343 * 100
    float* wsm  = sm + 343 * 100;     // transposed: [k*96 + c]
    int win = blockIdx.x;
    int tid = threadIdx.x;
    const float* inw = In + (size_t)win * WN * CDIM;
    for (int e = tid; e < WN * CDIM; e += blockDim.x)
        sin_[(e / 96) * 100 + (e % 96)] = inw[e];
    for (int e = tid; e < 96 * 27; e += blockDim.x) {
        int c = e / 27, k = e % 27;
        wsm[k * 96 + c] = Wt[e];
    }
    __syncthreads();
    if (tid >= WN) return;
    int t = tid;
    int dz = t / 49, r = t % 49, dy = r / 7, dx = r % 7;
    int  tn[27];
    bool val[27];
    #pragma unroll
    for (int k = 0; k < 27; k++) {
        int kd = k / 9, kh = (k / 3) % 3, kw = k % 3;
        int nz = dz + kd - 1, ny = dy + kh - 1, nx = dx + kw - 1;
        bool ok = (unsigned)nz < 7u && (unsigned)ny < 7u && (unsigned)nx < 7u;
        val[k] = ok;
        tn[k]  = ok ? (nz * 49 + ny * 7 + nx) : 0;
    }
    float* outw = Ot + (size_t)win * WN * CDIM + t * CDIM;
    for (int c4 = 0; c4 < 96; c4 += 4) {
        float4 a = *(const float4*)(Bi + c4);
        #pragma unroll
        for (int k = 0; k < 27; k++) {
            if (val[k]) {
                float4 iv = *(const float4*)(sin_ + tn[k] * 100 + c4);
                float4 wv = *(const float4*)(wsm + k * 96 + c4);
                a.x += iv.x * wv.x; a.y += iv.y * wv.y;
                a.z += iv.z * wv.z; a.w += iv.w * wv.w;
            }
        }
        *(float4*)(outw + c4) = a;
    }
}

// -------------------- attention: scores + shift-mask + softmax ---------------
__global__ __launch_bounds__(512)
void k_att1(const float* __restrict__ Q, const float* __restrict__ Km) {
    extern __shared__ float sm[];
    float* ks = sm;                  // 352 * 100 (pad rows)
    float* qs = sm + 352*100;        // 16 warps * 4 * 96
    int win = blockIdx.x;
    int tid = threadIdx.x, lane = tid & 31, wp = tid >> 5;
    const float* kw = Km + (size_t)win * WN * CDIM;
    for (int e = tid; e < WN * CDIM; e += 512)
        ks[(e / 96) * 100 + (e % 96)] = kw[e];
    __syncthreads();

    int ws = win >> 6, hs = (win >> 3) & 7, wd = win & 7;
    bool bz = (ws == 7), bh = (hs == 7), bw = (wd == 7);
    const float* qw = Q + (size_t)win * WN * CDIM;
    const float scale = 0.10206207261596575f; // 1/sqrt(96)
    float* myq = qs + wp * 384;

    // precompute per-lane m-row attributes as bitmasks over j
    unsigned mzm = 0, mhm = 0, mwm = 0, mvm = 0;
    #pragma unroll
    for (int j = 0; j < 11; j++) {
        int m = lane + 32*j;
        if (m < WN) {
            int dzm = m / 49, rm = m % 49, dym = rm / 7, dxm = rm % 7;
            if (dzm < 4) mzm |= 1u << j;
            if (dym < 4) mhm |= 1u << j;
            if (dxm < 4) mwm |= 1u << j;
            mvm |= 1u << j;
        }
    }

    for (int g = wp; g < 86; g += 16) {
        int q0 = g * 4;
        #pragma unroll
        for (int qi = 0; qi < 4; qi++) {
            int q = q0 + qi;
            if (q < WN) {
                myq[qi*96 + lane]      = qw[q*96 + lane]      * scale;
                myq[qi*96 + lane + 32] = qw[q*96 + lane + 32] * scale;
                myq[qi*96 + lane + 64] = qw[q*96 + lane + 64] * scale;
            }
        }
        __syncwarp();

        float acc[4][11];
        #pragma unroll
        for (int qi = 0; qi < 4; qi++)
            #pragma unroll
            for (int j = 0; j < 11; j++) acc[qi][j] = 0.f;

        #pragma unroll 6
        for (int c4 = 0; c4 < 24; c4++) {
            float4 qv0 = *(const float4*)(myq + 0*96 + c4*4);
            float4 qv1 = *(const float4*)(myq + 1*96 + c4*4);
            float4 qv2 = *(const float4*)(myq + 2*96 + c4*4);
            float4 qv3 = *(const float4*)(myq + 3*96 + c4*4);
            #pragma unroll
            for (int j = 0; j < 11; j++) {
                float4 kv = *(const float4*)(ks + (lane + 32*j)*100 + c4*4);
                acc[0][j] += kv.x*qv0.x + kv.y*qv0.y + kv.z*qv0.z + kv.w*qv0.w;
                acc[1][j] += kv.x*qv1.x + kv.y*qv1.y + kv.z*qv1.z + kv.w*qv1.w;
                acc[2][j] += kv.x*qv2.x + kv.y*qv2.y + kv.z*qv2.z + kv.w*qv2.w;
                acc[3][j] += kv.x*qv3.x + kv.y*qv3.y + kv.z*qv3.z + kv.w*qv3.w;
            }
        }

        #pragma unroll
        for (int qi = 0; qi < 4; qi++) {
            int q = q0 + qi;
            if (q >= WN) break;
            int dzq = q / 49, rq = q % 49, dyq = rq / 7, dxq = rq % 7;
            bool gz = dzq < 4, gh = dyq < 4, gw = dxq < 4;
            float mx = -1e30f;
            #pragma unroll
            for (int j = 0; j < 11; j++) {
                float v;
                if (mvm & (1u << j)) {
                    bool same = (!bz || (gz == ((mzm >> j) & 1))) &&
                                (!bh || (gh == ((mhm >> j) & 1))) &&
                                (!bw || (gw == ((mwm >> j) & 1)));
                    v = acc[qi][j] + (same ? 0.f : -100.f);
                } else v = -1e30f;
                acc[qi][j] = v;
                mx = fmaxf(mx, v);
            }
            #pragma unroll
            for (int o = 16; o; o >>= 1) mx = fmaxf(mx, __shfl_xor_sync(0xffffffffu, mx, o));
            float ssum = 0.f;
            #pragma unroll
            for (int j = 0; j < 11; j++) { acc[qi][j] = __expf(acc[qi][j] - mx); ssum += acc[qi][j]; }
            #pragma unroll
            for (int o = 16; o; o >>= 1) ssum += __shfl_xor_sync(0xffffffffu, ssum, o);
            float rinv = 1.f / ssum;
            float* arow = g_attn + ((size_t)win*WN + q)*WN;
            #pragma unroll
            for (int j = 0; j < 11; j++) {
                int m = lane + 32*j;
                if (m < WN) arow[m] = acc[qi][j] * rinv;
            }
        }
        __syncwarp();
    }
}

// -------------------- attention: P @ V, store axis-mixed (c*343 + n) ---------
__global__ __launch_bounds__(512)
void k_att2(const float* __restrict__ V) {
    extern __shared__ float sm[];
    float* vs = sm;                   // 343*100
    float* ps = sm + 343*100;         // 16 warps * 8*32
    float* st = ps + 16*256;          // 16 warps * 96*9
    int win = blockIdx.x;
    int tid = threadIdx.x, lane = tid & 31, wp = tid >> 5;
    const float* vw = V + (size_t)win * WN * CDIM;
    for (int e = tid; e < WN * CDIM; e += 512)
        vs[(e / 96) * 100 + (e % 96)] = vw[e];
    __syncthreads();

    float* myp  = ps + wp * 256;
    float* myst = st + wp * 864;
    float* ob   = g_ot + (size_t)win * WN * CDIM;

    for (int g = wp; g < 43; g += 16) {          // ceil(343/8)=43 groups of 8 q
        int q0 = g * 8;
        float acc[8][3] = {};
        for (int m0 = 0; m0 < WN; m0 += 32) {
            int mlen = WN - m0; if (mlen > 32) mlen = 32;
            #pragma unroll
            for (int qi = 0; qi < 8; qi++) {
                int q = q0 + qi;
                if (q < WN && lane < mlen)
                    myp[qi*32 + lane] = g_attn[((size_t)win*WN + q)*WN + m0 + lane];
            }
            __syncwarp();
            for (int mi = 0; mi < mlen; mi++) {
                float v0 = vs[(m0 + mi)*100 + lane];
                float v1 = vs[(m0 + mi)*100 + lane + 32];
                float v2 = vs[(m0 + mi)*100 + lane + 64];
                #pragma unroll
                for (int qi = 0; qi < 8; qi++) {
                    float p = myp[qi*32 + mi];
                    acc[qi][0] += p * v0;
                    acc[qi][1] += p * v1;
                    acc[qi][2] += p * v2;
                }
            }
            __syncwarp();
        }
        // transpose-stage then coalesced-ish scatter store
        #pragma unroll
        for (int qi = 0; qi < 8; qi++) {
            myst[(lane)     *9 + qi] = acc[qi][0];
            myst[(lane + 32)*9 + qi] = acc[qi][1];
            myst[(lane + 64)*9 + qi] = acc[qi][2];
        }
        __syncwarp();
        for (int e = lane; e < 768; e += 32) {
            int c = e >> 3, qq = e & 7;
            int q = q0 + qq;
            if (q < WN) ob[(size_t)c*WN + q] = myst[c*9 + qq];
        }
        __syncwarp();
    }
}

// -------------------- window-reverse + roll(+3) + residual + LN2 (fused) -----
__global__ __launch_bounds__(256)
void k_resln2(const float* __restrict__ x,
              const float* __restrict__ gg, const float* __restrict__ bb) {
    __shared__ float xs[32*101];
    int p0 = blockIdx.x * 32;
    int tid = threadIdx.x, lane = tid & 31, wp = tid >> 5;
    for (int e = tid; e < 96*32; e += 256) {
        int c = e >> 5, i = e & 31;
        xs[i*101 + c] = x[(size_t)c*NTOK + p0 + i];
    }
    __syncthreads();
    #pragma unroll
    for (int ii = wp; ii < 32; ii += 8) {
        int p = p0 + ii;
        int s = p / 3136, r = p % 3136, h = r / 56, w = r % 56;
        int s2 = (s >= 3) ? s - 3 : s + 53;
        int h2 = (h >= 3) ? h - 3 : h + 53;
        int w2 = (w >= 3) ? w - 3 : w + 53;
        int win = (s2/7)*64 + (h2/7)*8 + (w2/7);
        int np  = (s2%7)*49 + (h2%7)*7 + (w2%7);
        const float* ov = g_ot + (size_t)win*WN*CDIM + np*96;
        float v0 = xs[ii*101 + lane]      + ov[lane];
        float v1 = xs[ii*101 + lane + 32] + ov[lane + 32];
        float v2 = xs[ii*101 + lane + 64] + ov[lane + 64];
        float* xr = g_xres + (size_t)p*CDIM;
        xr[lane] = v0; xr[lane + 32] = v1; xr[lane + 64] = v2;
        float sum = v0 + v1 + v2, sq = v0*v0 + v1*v1 + v2*v2;
        #pragma unroll
        for (int o = 16; o; o >>= 1) {
            sum += __shfl_xor_sync(0xffffffffu, sum, o);
            sq  += __shfl_xor_sync(0xffffffffu, sq, o);
        }
        float mean = sum * (1.f/96.f);
        float var  = sq * (1.f/96.f) - mean*mean;
        float inv  = rsqrtf(var + 1e-5f);
        float* yo = g_ln2 + (size_t)p*CDIM;
        yo[lane]      = (v0 - mean)*inv*gg[lane]      + bb[lane];
        yo[lane + 32] = (v1 - mean)*inv*gg[lane + 32] + bb[lane + 32];
        yo[lane + 64] = (v2 - mean)*inv*gg[lane + 64] + bb[lane + 64];
    }
}

// -------------------- launch --------------------------------------------------
extern "C" void kernel_launch(void* const* d_in, const int* in_sizes, int n_in,
                              void* d_out, int out_size) {
    const float* x   = (const float*)d_in[0];
    const float* n1g = (const float*)d_in[1];
    const float* n1b = (const float*)d_in[2];
    const float* wq  = (const float*)d_in[3];
    const float* bq  = (const float*)d_in[4];
    const float* wk  = (const float*)d_in[5];
    const float* bk  = (const float*)d_in[6];
    const float* wv  = (const float*)d_in[7];
    const float* bv  = (const float*)d_in[8];
    const float* dqw = (const float*)d_in[9];
    const float* dqb = (const float*)d_in[10];
    const float* dkw = (const float*)d_in[11];
    const float* dkb = (const float*)d_in[12];
    const float* dvw = (const float*)d_in[13];
    const float* dvb = (const float*)d_in[14];
    const float* n2g = (const float*)d_in[15];
    const float* n2b = (const float*)d_in[16];
    const float* f1w = (const float*)d_in[17];
    const float* f1b = (const float*)d_in[18];
    const float* f2w = (const float*)d_in[19];
    const float* f2b = (const float*)d_in[20];
    float* out = (float*)d_out;

    float *pxw, *pqp, *pkp, *pvp, *pq, *pk, *pv, *pln2, *ph, *pxres, *pwqkv, *pbqkv;
    cudaGetSymbolAddress((void**)&pxw,   g_xw);
    cudaGetSymbolAddress((void**)&pqp,   g_qp);
    cudaGetSymbolAddress((void**)&pkp,   g_kp);
    cudaGetSymbolAddress((void**)&pvp,   g_vp);
    cudaGetSymbolAddress((void**)&pq,    g_q);
    cudaGetSymbolAddress((void**)&pk,    g_k);
    cudaGetSymbolAddress((void**)&pv,    g_v);
    cudaGetSymbolAddress((void**)&pln2,  g_ln2);
    cudaGetSymbolAddress((void**)&ph,    g_h);
    cudaGetSymbolAddress((void**)&pxres, g_xres);
    cudaGetSymbolAddress((void**)&pwqkv, g_wqkv);
    cudaGetSymbolAddress((void**)&pbqkv, g_bqkv);

    const int DW_SMEM   = (343*100 + 27*96) * 4;
    const int ATT1_SMEM = (352*100 + 16*4*96) * 4;
    const int ATT2_SMEM = (343*100 + 16*256 + 16*864) * 4;
    cudaFuncSetAttribute(k_dw,   cudaFuncAttributeMaxDynamicSharedMemorySize, DW_SMEM);
    cudaFuncSetAttribute(k_att1, cudaFuncAttributeMaxDynamicSharedMemorySize, ATT1_SMEM);
    cudaFuncSetAttribute(k_att2, cudaFuncAttributeMaxDynamicSharedMemorySize, ATT2_SMEM);

    // 0) pack qkv weights
    k_prep<<<(3*CDIM*CDIM + 255)/256, 256>>>(wq, bq, wk, bk, wv, bv);

    // 1) LN1 + roll + window gather (coalesced)
    k_ln1<<<NTOK/64, 256>>>(x, n1g, n1b);

    // 2) fused qkv conv1x1: one GEMM M=NTOK, N=288, K=96
    dim3 gq(NTOK/128, 3);
    k_gemm<3><<<gq, 256>>>(pxw, pwqkv, pbqkv, NTOK, 288, 96, pqp, pkp, pvp, nullptr, nullptr);

    // 3) depthwise 3x3x3 per window
    k_dw<<<NW, 352, DW_SMEM>>>(pqp, dqw, dqb, pq);
    k_dw<<<NW, 352, DW_SMEM>>>(pkp, dkw, dkb, pk);
    k_dw<<<NW, 352, DW_SMEM>>>(pvp, dvw, dvb, pv);

    // 4) attention
    k_att1<<<NW, 512, ATT1_SMEM>>>(pq, pk);
    k_att2<<<NW, 512, ATT2_SMEM>>>(pv);

    // 5) reverse + roll back + residual + LN2 (fused)
    k_resln2<<<NTOK/32, 256>>>(x, n2g, n2b);

    // 6) MLP
    dim3 g2(NTOK/128, HIDD/96);
    k_gemm<1><<<g2, 256>>>(pln2, f1w, f1b, NTOK, HIDD, 96, ph, nullptr, nullptr, nullptr, nullptr);
    dim3 g3(NTOK/128, 1);
    k_gemm<2><<<g3, 256>>>(ph, f2w, f2b, NTOK, 96, HIDD, nullptr, nullptr, nullptr, pxres, out);
}

// round 3
// speedup vs baseline: 1.5599x; 1.1502x over previous
#include <cuda_runtime.h>
#include <math.h>

#define NTOK 175616   // 56*56*56
#define CDIM 96
#define NW   512
#define WN   343
#define HIDD 384

// -------------------- scratch (device globals) -------------------------------
__device__ float g_xw  [NW*WN*CDIM];   // LN1 output, windowed (win, t, c)
__device__ float g_qp  [NW*WN*CDIM];
__device__ float g_kp  [NW*WN*CDIM];
__device__ float g_vp  [NW*WN*CDIM];
__device__ float g_q   [NW*WN*CDIM];
__device__ float g_k   [NW*WN*CDIM];
__device__ float g_v   [NW*WN*CDIM];
__device__ float g_attn[(size_t)NW*WN*WN]; // softmax probabilities
__device__ float g_ot  [NW*WN*CDIM];   // attention out, axis-mixed: flat = c*343 + n
__device__ float g_xres[NTOK*CDIM];    // residual stream (token-major)
__device__ float g_ln2 [NTOK*CDIM];
__device__ float g_h   [NTOK*HIDD];    // MLP hidden
__device__ float g_wqkv[3*CDIM*CDIM];
__device__ float g_bqkv[3*CDIM];

// -------------------- pack qkv weights ---------------------------------------
__global__ void k_prep(const float* __restrict__ wq, const float* __restrict__ bq,
                       const float* __restrict__ wk, const float* __restrict__ bk,
                       const float* __restrict__ wv, const float* __restrict__ bv) {
    int i = blockIdx.x * 256 + threadIdx.x;
    if (i < 3*CDIM*CDIM) {
        int t = i / (CDIM*CDIM), r = i % (CDIM*CDIM);
        g_wqkv[i] = (t == 0) ? wq[r] : (t == 1) ? wk[r] : wv[r];
    }
    if (i < 3*CDIM) {
        int t = i / CDIM, r = i % CDIM;
        g_bqkv[i] = (t == 0) ? bq[r] : (t == 1) ? bk[r] : bv[r];
    }
}

// -------------------- LN1 + roll(-3) + window partition (coalesced) ----------
__global__ __launch_bounds__(256)
void k_ln1(const float* __restrict__ x,
           const float* __restrict__ gg, const float* __restrict__ bb) {
    __shared__ float xs[64*101];
    int p0 = blockIdx.x * 64;
    int tid = threadIdx.x, lane = tid & 31, wp = tid >> 5;
    for (int e = tid; e < 96*64; e += 256) {
        int c = e >> 6, i = e & 63;
        xs[i*101 + c] = x[(size_t)c*NTOK + p0 + i];
    }
    __syncthreads();
    #pragma unroll
    for (int ii = wp; ii < 64; ii += 8) {
        int p = p0 + ii;
        int s = p / 3136, r = p % 3136, h = r / 56, w = r % 56;
        int s2 = (s >= 3) ? s - 3 : s + 53;
        int h2 = (h >= 3) ? h - 3 : h + 53;
        int w2 = (w >= 3) ? w - 3 : w + 53;
        int win = (s2/7)*64 + (h2/7)*8 + (w2/7);
        int t   = (s2%7)*49 + (h2%7)*7 + (w2%7);
        float v0 = xs[ii*101 + lane];
        float v1 = xs[ii*101 + lane + 32];
        float v2 = xs[ii*101 + lane + 64];
        float sum = v0 + v1 + v2, sq = v0*v0 + v1*v1 + v2*v2;
        #pragma unroll
        for (int o = 16; o; o >>= 1) {
            sum += __shfl_xor_sync(0xffffffffu, sum, o);
            sq  += __shfl_xor_sync(0xffffffffu, sq, o);
        }
        float mean = sum * (1.f/96.f);
        float var  = sq * (1.f/96.f) - mean*mean;
        float inv  = rsqrtf(var + 1e-5f);
        float* ob = g_xw + ((size_t)win*WN + t)*CDIM;
        ob[lane]      = (v0 - mean)*inv*gg[lane]      + bb[lane];
        ob[lane + 32] = (v1 - mean)*inv*gg[lane + 32] + bb[lane + 32];
        ob[lane + 64] = (v2 - mean)*inv*gg[lane + 64] + bb[lane + 64];
    }
}

// -------------------- tiled GEMM: Out[M,N] = A[M,K] @ W[N,K]^T + b -----------
// EPI: 0 plain, 1 GELU, 2 residual + transposed store, 3 qkv split
template<int EPI>
__global__ __launch_bounds__(256)
void k_gemm(const float* __restrict__ A, const float* __restrict__ W,
            const float* __restrict__ bias, int M, int Nout, int K,
            float* __restrict__ O0, float* __restrict__ O1, float* __restrict__ O2,
            const float* __restrict__ Res, float* __restrict__ OutT) {
    __shared__ float sm[32*132 + 32*98];
    float* As = sm;
    float* Bs = sm + 32*132;
    int bm = blockIdx.x * 128;
    int bn = blockIdx.y * 96;
    int tid = threadIdx.x, tx = tid & 15, ty = tid >> 4;
    int arow = tid >> 3, ak = (tid & 7) * 4;
    float acc[8][6] = {};

    for (int k0 = 0; k0 < K; k0 += 32) {
        #pragma unroll
        for (int l = 0; l < 4; l++) {
            int r = arow + l*32;
            float4 v = *(const float4*)(A + (size_t)(bm + r)*K + k0 + ak);
            As[(ak+0)*132 + r] = v.x;
            As[(ak+1)*132 + r] = v.y;
            As[(ak+2)*132 + r] = v.z;
            As[(ak+3)*132 + r] = v.w;
        }
        #pragma unroll
        for (int l = 0; l < 3; l++) {
            int c = arow + l*32;
            float4 v = *(const float4*)(W + (size_t)(bn + c)*K + k0 + ak);
            Bs[(ak+0)*98 + c] = v.x;
            Bs[(ak+1)*98 + c] = v.y;
            Bs[(ak+2)*98 + c] = v.z;
            Bs[(ak+3)*98 + c] = v.w;
        }
        __syncthreads();
        #pragma unroll
        for (int kk = 0; kk < 32; kk++) {
            float4 a0 = *(const float4*)(As + kk*132 + ty*8);
            float4 a1 = *(const float4*)(As + kk*132 + ty*8 + 4);
            float2 b0 = *(const float2*)(Bs + kk*98 + tx*6);
            float2 b1 = *(const float2*)(Bs + kk*98 + tx*6 + 2);
            float2 b2 = *(const float2*)(Bs + kk*98 + tx*6 + 4);
            float a[8] = {a0.x,a0.y,a0.z,a0.w,a1.x,a1.y,a1.z,a1.w};
            float b[6] = {b0.x,b0.y,b1.x,b1.y,b2.x,b2.y};
            #pragma unroll
            for (int i = 0; i < 8; i++)
                #pragma unroll
                for (int j = 0; j < 6; j++)
                    acc[i][j] += a[i]*b[j];
        }
        __syncthreads();
    }

    if (EPI == 3) {
        float* o = (blockIdx.y == 0) ? O0 : (blockIdx.y == 1) ? O1 : O2;
        #pragma unroll
        for (int i = 0; i < 8; i++) {
            int row = bm + ty*8 + i;
            #pragma unroll
            for (int j = 0; j < 6; j++) {
                int col = tx*6 + j;
                o[(size_t)row*96 + col] = acc[i][j] + bias[bn + col];
            }
        }
    } else if (EPI == 1) {
        #pragma unroll
        for (int i = 0; i < 8; i++) {
            int row = bm + ty*8 + i;
            #pragma unroll
            for (int j = 0; j < 6; j++) {
                int col = bn + tx*6 + j;
                float v = acc[i][j] + bias[col];
                v = 0.5f * v * (1.f + erff(v * 0.70710678118654752f));
                O0[(size_t)row*Nout + col] = v;
            }
        }
    } else if (EPI == 2) {
        float* st = sm;
        for (int c0 = 0; c0 < 96; c0 += 48) {
            if ((tx < 8) == (c0 == 0)) {
                #pragma unroll
                for (int i = 0; i < 8; i++) {
                    int row = ty*8 + i;
                    #pragma unroll
                    for (int j = 0; j < 6; j++) {
                        int col = tx*6 + j;
                        float v = acc[i][j] + bias[col] + Res[(size_t)(bm + row)*96 + col];
                        st[(col - c0)*132 + row] = v;
                    }
                }
            }
            __syncthreads();
            for (int e = tid; e < 48*128; e += 256) {
                int col = e >> 7, r = e & 127;
                OutT[(size_t)(c0 + col)*NTOK + bm + r] = st[col*132 + r];
            }
            __syncthreads();
        }
    } else {
        #pragma unroll
        for (int i = 0; i < 8; i++) {
            int row = bm + ty*8 + i;
            #pragma unroll
            for (int j = 0; j < 6; j++) {
                int col = bn + tx*6 + j;
                O0[(size_t)row*Nout + col] = acc[i][j] + bias[col];
            }
        }
    }
}

// -------------------- depthwise 3x3x3: channel-split, x-sliding-window -------
// grid (NW, 3): 32 channels per block. thread = (dz, dy, c4grp): 7*7*8 = 392.
#define FMA4(A, W, V) { A.x += (W).x*(V).x; A.y += (W).y*(V).y; \
                        A.z += (W).z*(V).z; A.w += (W).w*(V).w; }
__global__ __launch_bounds__(392, 2)
void k_dw(const float* __restrict__ In, const float* __restrict__ Wt,
          const float* __restrict__ Bi, float* __restrict__ Ot) {
    __shared__ float sin_[WN*32];
    __shared__ float wsm[27*32];   // [k*32 + cc]
    int win = blockIdx.x;
    int c0 = blockIdx.y * 32;
    int tid = threadIdx.x;
    const float* inw = In + (size_t)win*WN*CDIM + c0;
    for (int e = tid; e < WN*8; e += 392) {
        int t = e >> 3, c4 = e & 7;
        *(float4*)(sin_ + t*32 + c4*4) = *(const float4*)(inw + t*96 + c4*4);
    }
    for (int e = tid; e < 27*32; e += 392) {
        int k = e >> 5, cc = e & 31;
        wsm[k*32 + cc] = Wt[(c0 + cc)*27 + k];   // Wt: (C,1,3,3,3)
    }
    __syncthreads();

    int g = tid & 7, dy = (tid >> 3) % 7, dz = tid / 56;
    int cc = g * 4;
    float4 bias = *(const float4*)(Bi + c0 + cc);
    float4 acc[7];
    #pragma unroll
    for (int x = 0; x < 7; x++) acc[x] = bias;

    #pragma unroll
    for (int kd = 0; kd < 3; kd++) {
        int nz = dz + kd - 1;
        if ((unsigned)nz >= 7u) continue;
        #pragma unroll
        for (int kh = 0; kh < 3; kh++) {
            int ny = dy + kh - 1;
            if ((unsigned)ny >= 7u) continue;
            const float* row = sin_ + (nz*49 + ny*7)*32 + cc;
            float4 iv[7];
            #pragma unroll
            for (int x = 0; x < 7; x++) iv[x] = *(const float4*)(row + x*32);
            const float* wp_ = wsm + (kd*9 + kh*3)*32 + cc;
            float4 w0 = *(const float4*)(wp_);
            float4 w1 = *(const float4*)(wp_ + 32);
            float4 w2 = *(const float4*)(wp_ + 64);
            // kw = 0: out x reads in x-1  (x = 1..6)
            #pragma unroll
            for (int x = 1; x < 7; x++) FMA4(acc[x], w0, iv[x-1]);
            // kw = 1: out x reads in x    (x = 0..6)
            #pragma unroll
            for (int x = 0; x < 7; x++) FMA4(acc[x], w1, iv[x]);
            // kw = 2: out x reads in x+1  (x = 0..5)
            #pragma unroll
            for (int x = 0; x < 6; x++) FMA4(acc[x], w2, iv[x+1]);
        }
    }

    float* outw = Ot + (size_t)win*WN*CDIM + (dz*49 + dy*7)*96 + c0 + cc;
    #pragma unroll
    for (int x = 0; x < 7; x++)
        *(float4*)(outw + x*96) = acc[x];
}

// -------------------- attention: scores + shift-mask + softmax ---------------
__global__ __launch_bounds__(512)
void k_att1(const float* __restrict__ Q, const float* __restrict__ Km) {
    extern __shared__ float sm[];
    float* ks = sm;                  // 352 * 100 (pad rows)
    float* qs = sm + 352*100;        // 16 warps * 4 * 96
    int win = blockIdx.x;
    int tid = threadIdx.x, lane = tid & 31, wp = tid >> 5;
    const float* kw = Km + (size_t)win * WN * CDIM;
    for (int e = tid; e < WN * CDIM; e += 512)
        ks[(e / 96) * 100 + (e % 96)] = kw[e];
    __syncthreads();

    int ws = win >> 6, hs = (win >> 3) & 7, wd = win & 7;
    bool bz = (ws == 7), bh = (hs == 7), bw = (wd == 7);
    const float* qw = Q + (size_t)win * WN * CDIM;
    const float scale = 0.10206207261596575f; // 1/sqrt(96)
    float* myq = qs + wp * 384;

    unsigned mzm = 0, mhm = 0, mwm = 0, mvm = 0;
    #pragma unroll
    for (int j = 0; j < 11; j++) {
        int m = lane + 32*j;
        if (m < WN) {
            int dzm = m / 49, rm = m % 49, dym = rm / 7, dxm = rm % 7;
            if (dzm < 4) mzm |= 1u << j;
            if (dym < 4) mhm |= 1u << j;
            if (dxm < 4) mwm |= 1u << j;
            mvm |= 1u << j;
        }
    }

    for (int g = wp; g < 86; g += 16) {
        int q0 = g * 4;
        #pragma unroll
        for (int qi = 0; qi < 4; qi++) {
            int q = q0 + qi;
            if (q < WN) {
                myq[qi*96 + lane]      = qw[q*96 + lane]      * scale;
                myq[qi*96 + lane + 32] = qw[q*96 + lane + 32] * scale;
                myq[qi*96 + lane + 64] = qw[q*96 + lane + 64] * scale;
            }
        }
        __syncwarp();

        float acc[4][11];
        #pragma unroll
        for (int qi = 0; qi < 4; qi++)
            #pragma unroll
            for (int j = 0; j < 11; j++) acc[qi][j] = 0.f;

        #pragma unroll 6
        for (int c4 = 0; c4 < 24; c4++) {
            float4 qv0 = *(const float4*)(myq + 0*96 + c4*4);
            float4 qv1 = *(const float4*)(myq + 1*96 + c4*4);
            float4 qv2 = *(const float4*)(myq + 2*96 + c4*4);
            float4 qv3 = *(const float4*)(myq + 3*96 + c4*4);
            #pragma unroll
            for (int j = 0; j < 11; j++) {
                float4 kv = *(const float4*)(ks + (lane + 32*j)*100 + c4*4);
                acc[0][j] += kv.x*qv0.x + kv.y*qv0.y + kv.z*qv0.z + kv.w*qv0.w;
                acc[1][j] += kv.x*qv1.x + kv.y*qv1.y + kv.z*qv1.z + kv.w*qv1.w;
                acc[2][j] += kv.x*qv2.x + kv.y*qv2.y + kv.z*qv2.z + kv.w*qv2.w;
                acc[3][j] += kv.x*qv3.x + kv.y*qv3.y + kv.z*qv3.z + kv.w*qv3.w;
            }
        }

        #pragma unroll
        for (int qi = 0; qi < 4; qi++) {
            int q = q0 + qi;
            if (q >= WN) break;
            int dzq = q / 49, rq = q % 49, dyq = rq / 7, dxq = rq % 7;
            bool gz = dzq < 4, gh = dyq < 4, gw = dxq < 4;
            float mx = -1e30f;
            #pragma unroll
            for (int j = 0; j < 11; j++) {
                float v;
                if (mvm & (1u << j)) {
                    bool same = (!bz || (gz == ((mzm >> j) & 1))) &&
                                (!bh || (gh == ((mhm >> j) & 1))) &&
                                (!bw || (gw == ((mwm >> j) & 1)));
                    v = acc[qi][j] + (same ? 0.f : -100.f);
                } else v = -1e30f;
                acc[qi][j] = v;
                mx = fmaxf(mx, v);
            }
            #pragma unroll
            for (int o = 16; o; o >>= 1) mx = fmaxf(mx, __shfl_xor_sync(0xffffffffu, mx, o));
            float ssum = 0.f;
            #pragma unroll
            for (int j = 0; j < 11; j++) { acc[qi][j] = __expf(acc[qi][j] - mx); ssum += acc[qi][j]; }
            #pragma unroll
            for (int o = 16; o; o >>= 1) ssum += __shfl_xor_sync(0xffffffffu, ssum, o);
            float rinv = 1.f / ssum;
            float* arow = g_attn + ((size_t)win*WN + q)*WN;
            #pragma unroll
            for (int j = 0; j < 11; j++) {
                int m = lane + 32*j;
                if (m < WN) arow[m] = acc[qi][j] * rinv;
            }
        }
        __syncwarp();
    }
}

// -------------------- attention: P @ V, store axis-mixed (c*343 + n) ---------
__global__ __launch_bounds__(512)
void k_att2(const float* __restrict__ V) {
    extern __shared__ float sm[];
    float* vs = sm;                   // 343*100
    float* ps = sm + 343*100;         // 16 warps * 8*32
    float* st = ps + 16*256;          // 16 warps * 96*9
    int win = blockIdx.x;
    int tid = threadIdx.x, lane = tid & 31, wp = tid >> 5;
    const float* vw = V + (size_t)win * WN * CDIM;
    for (int e = tid; e < WN * CDIM; e += 512)
        vs[(e / 96) * 100 + (e % 96)] = vw[e];
    __syncthreads();

    float* myp  = ps + wp * 256;
    float* myst = st + wp * 864;
    float* ob   = g_ot + (size_t)win * WN * CDIM;

    for (int g = wp; g < 43; g += 16) {
        int q0 = g * 8;
        float acc[8][3] = {};
        for (int m0 = 0; m0 < WN; m0 += 32) {
            int mlen = WN - m0; if (mlen > 32) mlen = 32;
            #pragma unroll
            for (int qi = 0; qi < 8; qi++) {
                int q = q0 + qi;
                if (q < WN && lane < mlen)
                    myp[qi*32 + lane] = g_attn[((size_t)win*WN + q)*WN + m0 + lane];
            }
            __syncwarp();
            for (int mi = 0; mi < mlen; mi++) {
                float v0 = vs[(m0 + mi)*100 + lane];
                float v1 = vs[(m0 + mi)*100 + lane + 32];
                float v2 = vs[(m0 + mi)*100 + lane + 64];
                #pragma unroll
                for (int qi = 0; qi < 8; qi++) {
                    float p = myp[qi*32 + mi];
                    acc[qi][0] += p * v0;
                    acc[qi][1] += p * v1;
                    acc[qi][2] += p * v2;
                }
            }
            __syncwarp();
        }
        #pragma unroll
        for (int qi = 0; qi < 8; qi++) {
            myst[(lane)     *9 + qi] = acc[qi][0];
            myst[(lane + 32)*9 + qi] = acc[qi][1];
            myst[(lane + 64)*9 + qi] = acc[qi][2];
        }
        __syncwarp();
        for (int e = lane; e < 768; e += 32) {
            int c = e >> 3, qq = e & 7;
            int q = q0 + qq;
            if (q < WN) ob[(size_t)c*WN + q] = myst[c*9 + qq];
        }
        __syncwarp();
    }
}

// -------------------- window-reverse + roll(+3) + residual + LN2 (fused) -----
__global__ __launch_bounds__(256)
void k_resln2(const float* __restrict__ x,
              const float* __restrict__ gg, const float* __restrict__ bb) {
    __shared__ float xs[32*101];
    int p0 = blockIdx.x * 32;
    int tid = threadIdx.x, lane = tid & 31, wp = tid >> 5;
    for (int e = tid; e < 96*32; e += 256) {
        int c = e >> 5, i = e & 31;
        xs[i*101 + c] = x[(size_t)c*NTOK + p0 + i];
    }
    __syncthreads();
    #pragma unroll
    for (int ii = wp; ii < 32; ii += 8) {
        int p = p0 + ii;
        int s = p / 3136, r = p % 3136, h = r / 56, w = r % 56;
        int s2 = (s >= 3) ? s - 3 : s + 53;
        int h2 = (h >= 3) ? h - 3 : h + 53;
        int w2 = (w >= 3) ? w - 3 : w + 53;
        int win = (s2/7)*64 + (h2/7)*8 + (w2/7);
        int np  = (s2%7)*49 + (h2%7)*7 + (w2%7);
        const float* ov = g_ot + (size_t)win*WN*CDIM + np*96;
        float v0 = xs[ii*101 + lane]      + ov[lane];
        float v1 = xs[ii*101 + lane + 32] + ov[lane + 32];
        float v2 = xs[ii*101 + lane + 64] + ov[lane + 64];
        float* xr = g_xres + (size_t)p*CDIM;
        xr[lane] = v0; xr[lane + 32] = v1; xr[lane + 64] = v2;
        float sum = v0 + v1 + v2, sq = v0*v0 + v1*v1 + v2*v2;
        #pragma unroll
        for (int o = 16; o; o >>= 1) {
            sum += __shfl_xor_sync(0xffffffffu, sum, o);
            sq  += __shfl_xor_sync(0xffffffffu, sq, o);
        }
        float mean = sum * (1.f/96.f);
        float var  = sq * (1.f/96.f) - mean*mean;
        float inv  = rsqrtf(var + 1e-5f);
        float* yo = g_ln2 + (size_t)p*CDIM;
        yo[lane]      = (v0 - mean)*inv*gg[lane]      + bb[lane];
        yo[lane + 32] = (v1 - mean)*inv*gg[lane + 32] + bb[lane + 32];
        yo[lane + 64] = (v2 - mean)*inv*gg[lane + 64] + bb[lane + 64];
    }
}

// -------------------- launch --------------------------------------------------
extern "C" void kernel_launch(void* const* d_in, const int* in_sizes, int n_in,
                              void* d_out, int out_size) {
    const float* x   = (const float*)d_in[0];
    const float* n1g = (const float*)d_in[1];
    const float* n1b = (const float*)d_in[2];
    const float* wq  = (const float*)d_in[3];
    const float* bq  = (const float*)d_in[4];
    const float* wk  = (const float*)d_in[5];
    const float* bk  = (const float*)d_in[6];
    const float* wv  = (const float*)d_in[7];
    const float* bv  = (const float*)d_in[8];
    const float* dqw = (const float*)d_in[9];
    const float* dqb = (const float*)d_in[10];
    const float* dkw = (const float*)d_in[11];
    const float* dkb = (const float*)d_in[12];
    const float* dvw = (const float*)d_in[13];
    const float* dvb = (const float*)d_in[14];
    const float* n2g = (const float*)d_in[15];
    const float* n2b = (const float*)d_in[16];
    const float* f1w = (const float*)d_in[17];
    const float* f1b = (const float*)d_in[18];
    const float* f2w = (const float*)d_in[19];
    const float* f2b = (const float*)d_in[20];
    float* out = (float*)d_out;

    float *pxw, *pqp, *pkp, *pvp, *pq, *pk, *pv, *pln2, *ph, *pxres, *pwqkv, *pbqkv;
    cudaGetSymbolAddress((void**)&pxw,   g_xw);
    cudaGetSymbolAddress((void**)&pqp,   g_qp);
    cudaGetSymbolAddress((void**)&pkp,   g_kp);
    cudaGetSymbolAddress((void**)&pvp,   g_vp);
    cudaGetSymbolAddress((void**)&pq,    g_q);
    cudaGetSymbolAddress((void**)&pk,    g_k);
    cudaGetSymbolAddress((void**)&pv,    g_v);
    cudaGetSymbolAddress((void**)&pln2,  g_ln2);
    cudaGetSymbolAddress((void**)&ph,    g_h);
    cudaGetSymbolAddress((void**)&pxres, g_xres);
    cudaGetSymbolAddress((void**)&pwqkv, g_wqkv);
    cudaGetSymbolAddress((void**)&pbqkv, g_bqkv);

    const int ATT1_SMEM = (352*100 + 16*4*96) * 4;
    const int ATT2_SMEM = (343*100 + 16*256 + 16*864) * 4;
    cudaFuncSetAttribute(k_att1, cudaFuncAttributeMaxDynamicSharedMemorySize, ATT1_SMEM);
    cudaFuncSetAttribute(k_att2, cudaFuncAttributeMaxDynamicSharedMemorySize, ATT2_SMEM);

    // 0) pack qkv weights
    k_prep<<<(3*CDIM*CDIM + 255)/256, 256>>>(wq, bq, wk, bk, wv, bv);

    // 1) LN1 + roll + window gather (coalesced)
    k_ln1<<<NTOK/64, 256>>>(x, n1g, n1b);

    // 2) fused qkv conv1x1: one GEMM M=NTOK, N=288, K=96
    dim3 gq(NTOK/128, 3);
    k_gemm<3><<<gq, 256>>>(pxw, pwqkv, pbqkv, NTOK, 288, 96, pqp, pkp, pvp, nullptr, nullptr);

    // 3) depthwise 3x3x3 per window (channel-split)
    dim3 gdw(NW, 3);
    k_dw<<<gdw, 392>>>(pqp, dqw, dqb, pq);
    k_dw<<<gdw, 392>>>(pkp, dkw, dkb, pk);
    k_dw<<<gdw, 392>>>(pvp, dvw, dvb, pv);

    // 4) attention
    k_att1<<<NW, 512, ATT1_SMEM>>>(pq, pk);
    k_att2<<<NW, 512, ATT2_SMEM>>>(pv);

    // 5) reverse + roll back + residual + LN2 (fused)
    k_resln2<<<NTOK/32, 256>>>(x, n2g, n2b);

    // 6) MLP
    dim3 g2(NTOK/128, HIDD/96);
    k_gemm<1><<<g2, 256>>>(pln2, f1w, f1b, NTOK, HIDD, 96, ph, nullptr, nullptr, nullptr, nullptr);
    dim3 g3(NTOK/128, 1);
    k_gemm<2><<<g3, 256>>>(ph, f2w, f2b, NTOK, 96, HIDD, nullptr, nullptr, nullptr, pxres, out);
}

// round 4
// speedup vs baseline: 1.6283x; 1.0438x over previous
#include <cuda_runtime.h>
#include <math.h>

#define NTOK 175616   // 56*56*56
#define CDIM 96
#define NW   512
#define WN   343
#define HIDD 384

typedef unsigned long long u64;
union F4U { float4 f; ulonglong2 u; };

__device__ __forceinline__ u64 ffma2(u64 a, u64 b, u64 c) {
    u64 d; asm("fma.rn.f32x2 %0, %1, %2, %3;" : "=l"(d) : "l"(a), "l"(b), "l"(c));
    return d;
}
__device__ __forceinline__ u64 pack2(float lo, float hi) {
    u64 r; asm("mov.b64 %0, {%1, %2};" : "=l"(r) : "f"(lo), "f"(hi));
    return r;
}
__device__ __forceinline__ float2 unpack2(u64 v) {
    float2 r; asm("mov.b64 {%0, %1}, %2;" : "=f"(r.x), "=f"(r.y) : "l"(v));
    return r;
}
__device__ __forceinline__ float hadd2(u64 v) { float2 t = unpack2(v); return t.x + t.y; }

// -------------------- scratch (device globals) -------------------------------
__device__ float g_xw  [NW*WN*CDIM];
__device__ float g_qp  [NW*WN*CDIM];
__device__ float g_kp  [NW*WN*CDIM];
__device__ float g_vp  [NW*WN*CDIM];
__device__ float g_q   [NW*WN*CDIM];
__device__ float g_k   [NW*WN*CDIM];
__device__ float g_v   [NW*WN*CDIM];
__device__ float g_attn[(size_t)NW*WN*WN];
__device__ float g_ot  [NW*WN*CDIM];   // attention out, axis-mixed: flat = c*343 + n
__device__ float g_xres[NTOK*CDIM];
__device__ float g_ln2 [NTOK*CDIM];
__device__ float g_h   [NTOK*HIDD];
__device__ float g_wqkv[3*CDIM*CDIM];
__device__ float g_bqkv[3*CDIM];

// -------------------- pack qkv weights ---------------------------------------
__global__ void k_prep(const float* __restrict__ wq, const float* __restrict__ bq,
                       const float* __restrict__ wk, const float* __restrict__ bk,
                       const float* __restrict__ wv, const float* __restrict__ bv) {
    int i = blockIdx.x * 256 + threadIdx.x;
    if (i < 3*CDIM*CDIM) {
        int t = i / (CDIM*CDIM), r = i % (CDIM*CDIM);
        g_wqkv[i] = (t == 0) ? wq[r] : (t == 1) ? wk[r] : wv[r];
    }
    if (i < 3*CDIM) {
        int t = i / CDIM, r = i % CDIM;
        g_bqkv[i] = (t == 0) ? bq[r] : (t == 1) ? bk[r] : bv[r];
    }
}

// -------------------- LN1 + roll(-3) + window partition (coalesced) ----------
__global__ __launch_bounds__(256)
void k_ln1(const float* __restrict__ x,
           const float* __restrict__ gg, const float* __restrict__ bb) {
    __shared__ float xs[64*101];
    int p0 = blockIdx.x * 64;
    int tid = threadIdx.x, lane = tid & 31, wp = tid >> 5;
    for (int e = tid; e < 96*64; e += 256) {
        int c = e >> 6, i = e & 63;
        xs[i*101 + c] = x[(size_t)c*NTOK + p0 + i];
    }
    __syncthreads();
    #pragma unroll
    for (int ii = wp; ii < 64; ii += 8) {
        int p = p0 + ii;
        int s = p / 3136, r = p % 3136, h = r / 56, w = r % 56;
        int s2 = (s >= 3) ? s - 3 : s + 53;
        int h2 = (h >= 3) ? h - 3 : h + 53;
        int w2 = (w >= 3) ? w - 3 : w + 53;
        int win = (s2/7)*64 + (h2/7)*8 + (w2/7);
        int t   = (s2%7)*49 + (h2%7)*7 + (w2%7);
        float v0 = xs[ii*101 + lane];
        float v1 = xs[ii*101 + lane + 32];
        float v2 = xs[ii*101 + lane + 64];
        float sum = v0 + v1 + v2, sq = v0*v0 + v1*v1 + v2*v2;
        #pragma unroll
        for (int o = 16; o; o >>= 1) {
            sum += __shfl_xor_sync(0xffffffffu, sum, o);
            sq  += __shfl_xor_sync(0xffffffffu, sq, o);
        }
        float mean = sum * (1.f/96.f);
        float var  = sq * (1.f/96.f) - mean*mean;
        float inv  = rsqrtf(var + 1e-5f);
        float* ob = g_xw + ((size_t)win*WN + t)*CDIM;
        ob[lane]      = (v0 - mean)*inv*gg[lane]      + bb[lane];
        ob[lane + 32] = (v1 - mean)*inv*gg[lane + 32] + bb[lane + 32];
        ob[lane + 64] = (v2 - mean)*inv*gg[lane + 64] + bb[lane + 64];
    }
}

// -------------------- tiled GEMM (packed f32x2 core) -------------------------
// EPI: 0 plain, 1 GELU, 2 residual + transposed store, 3 qkv split
template<int EPI>
__global__ __launch_bounds__(256)
void k_gemm(const float* __restrict__ A, const float* __restrict__ W,
            const float* __restrict__ bias, int M, int Nout, int K,
            float* __restrict__ O0, float* __restrict__ O1, float* __restrict__ O2,
            const float* __restrict__ Res, float* __restrict__ OutT) {
    __shared__ float sm[32*132 + 32*98];
    float* As = sm;
    float* Bs = sm + 32*132;
    int bm = blockIdx.x * 128;
    int bn = blockIdx.y * 96;
    int tid = threadIdx.x, tx = tid & 15, ty = tid >> 4;
    int arow = tid >> 3, ak = (tid & 7) * 4;
    u64 acc2[4][6] = {};   // row-pairs x 6 cols

    for (int k0 = 0; k0 < K; k0 += 32) {
        #pragma unroll
        for (int l = 0; l < 4; l++) {
            int r = arow + l*32;
            float4 v = *(const float4*)(A + (size_t)(bm + r)*K + k0 + ak);
            As[(ak+0)*132 + r] = v.x;
            As[(ak+1)*132 + r] = v.y;
            As[(ak+2)*132 + r] = v.z;
            As[(ak+3)*132 + r] = v.w;
        }
        #pragma unroll
        for (int l = 0; l < 3; l++) {
            int c = arow + l*32;
            float4 v = *(const float4*)(W + (size_t)(bn + c)*K + k0 + ak);
            Bs[(ak+0)*98 + c] = v.x;
            Bs[(ak+1)*98 + c] = v.y;
            Bs[(ak+2)*98 + c] = v.z;
            Bs[(ak+3)*98 + c] = v.w;
        }
        __syncthreads();
        #pragma unroll
        for (int kk = 0; kk < 32; kk++) {
            F4U A0, A1;
            A0.f = *(const float4*)(As + kk*132 + ty*8);
            A1.f = *(const float4*)(As + kk*132 + ty*8 + 4);
            float2 b0 = *(const float2*)(Bs + kk*98 + tx*6);
            float2 b1 = *(const float2*)(Bs + kk*98 + tx*6 + 2);
            float2 b2 = *(const float2*)(Bs + kk*98 + tx*6 + 4);
            u64 aa[4] = {A0.u.x, A0.u.y, A1.u.x, A1.u.y};
            u64 bb[6] = {pack2(b0.x,b0.x), pack2(b0.y,b0.y),
                         pack2(b1.x,b1.x), pack2(b1.y,b1.y),
                         pack2(b2.x,b2.x), pack2(b2.y,b2.y)};
            #pragma unroll
            for (int i = 0; i < 4; i++)
                #pragma unroll
                for (int j = 0; j < 6; j++)
                    acc2[i][j] = ffma2(aa[i], bb[j], acc2[i][j]);
        }
        __syncthreads();
    }

    float acc[8][6];
    #pragma unroll
    for (int i2 = 0; i2 < 4; i2++)
        #pragma unroll
        for (int j = 0; j < 6; j++) {
            float2 t = unpack2(acc2[i2][j]);
            acc[2*i2][j] = t.x;
            acc[2*i2+1][j] = t.y;
        }

    if (EPI == 3) {
        float* o = (blockIdx.y == 0) ? O0 : (blockIdx.y == 1) ? O1 : O2;
        #pragma unroll
        for (int i = 0; i < 8; i++) {
            int row = bm + ty*8 + i;
            #pragma unroll
            for (int j = 0; j < 6; j++) {
                int col = tx*6 + j;
                o[(size_t)row*96 + col] = acc[i][j] + bias[bn + col];
            }
        }
    } else if (EPI == 1) {
        #pragma unroll
        for (int i = 0; i < 8; i++) {
            int row = bm + ty*8 + i;
            #pragma unroll
            for (int j = 0; j < 6; j++) {
                int col = bn + tx*6 + j;
                float v = acc[i][j] + bias[col];
                v = 0.5f * v * (1.f + erff(v * 0.70710678118654752f));
                O0[(size_t)row*Nout + col] = v;
            }
        }
    } else if (EPI == 2) {
        float* st = sm;
        for (int c0 = 0; c0 < 96; c0 += 48) {
            if ((tx < 8) == (c0 == 0)) {
                #pragma unroll
                for (int i = 0; i < 8; i++) {
                    int row = ty*8 + i;
                    #pragma unroll
                    for (int j = 0; j < 6; j++) {
                        int col = tx*6 + j;
                        float v = acc[i][j] + bias[col] + Res[(size_t)(bm + row)*96 + col];
                        st[(col - c0)*132 + row] = v;
                    }
                }
            }
            __syncthreads();
            for (int e = tid; e < 48*128; e += 256) {
                int col = e >> 7, r = e & 127;
                OutT[(size_t)(c0 + col)*NTOK + bm + r] = st[col*132 + r];
            }
            __syncthreads();
        }
    } else {
        #pragma unroll
        for (int i = 0; i < 8; i++) {
            int row = bm + ty*8 + i;
            #pragma unroll
            for (int j = 0; j < 6; j++) {
                int col = bn + tx*6 + j;
                O0[(size_t)row*Nout + col] = acc[i][j] + bias[col];
            }
        }
    }
}

// -------------------- depthwise 3x3x3 (packed) --------------------------------
__global__ __launch_bounds__(392, 2)
void k_dw(const float* __restrict__ In, const float* __restrict__ Wt,
          const float* __restrict__ Bi, float* __restrict__ Ot) {
    __shared__ float sin_[WN*32];
    __shared__ float wsm[27*32];
    int win = blockIdx.x;
    int c0 = blockIdx.y * 32;
    int tid = threadIdx.x;
    const float* inw = In + (size_t)win*WN*CDIM + c0;
    for (int e = tid; e < WN*8; e += 392) {
        int t = e >> 3, c4 = e & 7;
        *(float4*)(sin_ + t*32 + c4*4) = *(const float4*)(inw + t*96 + c4*4);
    }
    for (int e = tid; e < 27*32; e += 392) {
        int k = e >> 5, cc = e & 31;
        wsm[k*32 + cc] = Wt[(c0 + cc)*27 + k];
    }
    __syncthreads();

    int g = tid & 7, dy = (tid >> 3) % 7, dz = tid / 56;
    int cc = g * 4;
    F4U bias4; bias4.f = *(const float4*)(Bi + c0 + cc);
    u64 ax[7], ay[7];
    #pragma unroll
    for (int x = 0; x < 7; x++) { ax[x] = bias4.u.x; ay[x] = bias4.u.y; }

    #pragma unroll
    for (int kd = 0; kd < 3; kd++) {
        int nz = dz + kd - 1;
        if ((unsigned)nz >= 7u) continue;
        #pragma unroll
        for (int kh = 0; kh < 3; kh++) {
            int ny = dy + kh - 1;
            if ((unsigned)ny >= 7u) continue;
            const float* row = sin_ + (nz*49 + ny*7)*32 + cc;
            F4U iv[7];
            #pragma unroll
            for (int x = 0; x < 7; x++) iv[x].f = *(const float4*)(row + x*32);
            const float* wp_ = wsm + (kd*9 + kh*3)*32 + cc;
            F4U w0, w1, w2;
            w0.f = *(const float4*)(wp_);
            w1.f = *(const float4*)(wp_ + 32);
            w2.f = *(const float4*)(wp_ + 64);
            #pragma unroll
            for (int x = 1; x < 7; x++) {
                ax[x] = ffma2(w0.u.x, iv[x-1].u.x, ax[x]);
                ay[x] = ffma2(w0.u.y, iv[x-1].u.y, ay[x]);
            }
            #pragma unroll
            for (int x = 0; x < 7; x++) {
                ax[x] = ffma2(w1.u.x, iv[x].u.x, ax[x]);
                ay[x] = ffma2(w1.u.y, iv[x].u.y, ay[x]);
            }
            #pragma unroll
            for (int x = 0; x < 6; x++) {
                ax[x] = ffma2(w2.u.x, iv[x+1].u.x, ax[x]);
                ay[x] = ffma2(w2.u.y, iv[x+1].u.y, ay[x]);
            }
        }
    }

    float* outw = Ot + (size_t)win*WN*CDIM + (dz*49 + dy*7)*96 + c0 + cc;
    #pragma unroll
    for (int x = 0; x < 7; x++) {
        F4U o; o.u.x = ax[x]; o.u.y = ay[x];
        *(float4*)(outw + x*96) = o.f;
    }
}

// -------------------- att1 helper: 4 queries x JN keys packed dot ------------
template<int JB, int JN>
__device__ __forceinline__ void qk_dot(const float* __restrict__ ks,
                                       const float* __restrict__ myq,
                                       int lane, float sc[4][11]) {
    u64 acc2[4][JN];
    #pragma unroll
    for (int qi = 0; qi < 4; qi++)
        #pragma unroll
        for (int jj = 0; jj < JN; jj++) acc2[qi][jj] = 0ull;

    #pragma unroll 4
    for (int c4 = 0; c4 < 24; c4++) {
        F4U qv0, qv1, qv2, qv3;
        qv0.f = *(const float4*)(myq + 0*96 + c4*4);
        qv1.f = *(const float4*)(myq + 1*96 + c4*4);
        qv2.f = *(const float4*)(myq + 2*96 + c4*4);
        qv3.f = *(const float4*)(myq + 3*96 + c4*4);
        #pragma unroll
        for (int jj = 0; jj < JN; jj++) {
            F4U kv;
            kv.f = *(const float4*)(ks + (lane + 32*(JB + jj))*100 + c4*4);
            acc2[0][jj] = ffma2(kv.u.x, qv0.u.x, acc2[0][jj]);
            acc2[0][jj] = ffma2(kv.u.y, qv0.u.y, acc2[0][jj]);
            acc2[1][jj] = ffma2(kv.u.x, qv1.u.x, acc2[1][jj]);
            acc2[1][jj] = ffma2(kv.u.y, qv1.u.y, acc2[1][jj]);
            acc2[2][jj] = ffma2(kv.u.x, qv2.u.x, acc2[2][jj]);
            acc2[2][jj] = ffma2(kv.u.y, qv2.u.y, acc2[2][jj]);
            acc2[3][jj] = ffma2(kv.u.x, qv3.u.x, acc2[3][jj]);
            acc2[3][jj] = ffma2(kv.u.y, qv3.u.y, acc2[3][jj]);
        }
    }
    #pragma unroll
    for (int qi = 0; qi < 4; qi++)
        #pragma unroll
        for (int jj = 0; jj < JN; jj++)
            sc[qi][JB + jj] = hadd2(acc2[qi][jj]);
}

// -------------------- attention: scores + shift-mask + softmax ---------------
__global__ __launch_bounds__(384)
void k_att1(const float* __restrict__ Q, const float* __restrict__ Km) {
    extern __shared__ float sm[];
    float* ks = sm;                  // 352 * 100
    float* qs = sm + 352*100;        // 12 warps * 384
    int win = blockIdx.x;
    int tid = threadIdx.x, lane = tid & 31, wp = tid >> 5;
    const float* kw = Km + (size_t)win * WN * CDIM;
    for (int e = tid; e < WN * CDIM; e += 384)
        ks[(e / 96) * 100 + (e % 96)] = kw[e];
    __syncthreads();

    int ws = win >> 6, hs = (win >> 3) & 7, wd = win & 7;
    bool bz = (ws == 7), bh = (hs == 7), bw = (wd == 7);
    const float* qw = Q + (size_t)win * WN * CDIM;
    const float scale = 0.10206207261596575f; // 1/sqrt(96)
    float* myq = qs + wp * 384;

    unsigned mzm = 0, mhm = 0, mwm = 0, mvm = 0;
    #pragma unroll
    for (int j = 0; j < 11; j++) {
        int m = lane + 32*j;
        if (m < WN) {
            int dzm = m / 49, rm = m % 49, dym = rm / 7, dxm = rm % 7;
            if (dzm < 4) mzm |= 1u << j;
            if (dym < 4) mhm |= 1u << j;
            if (dxm < 4) mwm |= 1u << j;
            mvm |= 1u << j;
        }
    }

    for (int g = wp; g < 86; g += 12) {
        int q0 = g * 4;
        #pragma unroll
        for (int qi = 0; qi < 4; qi++) {
            int q = q0 + qi;
            if (q < WN) {
                myq[qi*96 + lane]      = qw[q*96 + lane]      * scale;
                myq[qi*96 + lane + 32] = qw[q*96 + lane + 32] * scale;
                myq[qi*96 + lane + 64] = qw[q*96 + lane + 64] * scale;
            }
        }
        __syncwarp();

        float sc[4][11];
        qk_dot<0, 6>(ks, myq, lane, sc);
        qk_dot<6, 5>(ks, myq, lane, sc);

        #pragma unroll
        for (int qi = 0; qi < 4; qi++) {
            int q = q0 + qi;
            if (q >= WN) break;
            int dzq = q / 49, rq = q % 49, dyq = rq / 7, dxq = rq % 7;
            bool gz = dzq < 4, gh = dyq < 4, gw = dxq < 4;
            float mx = -1e30f;
            #pragma unroll
            for (int j = 0; j < 11; j++) {
                float v;
                if (mvm & (1u << j)) {
                    bool same = (!bz || (gz == ((mzm >> j) & 1))) &&
                                (!bh || (gh == ((mhm >> j) & 1))) &&
                                (!bw || (gw == ((mwm >> j) & 1)));
                    v = sc[qi][j] + (same ? 0.f : -100.f);
                } else v = -1e30f;
                sc[qi][j] = v;
                mx = fmaxf(mx, v);
            }
            #pragma unroll
            for (int o = 16; o; o >>= 1) mx = fmaxf(mx, __shfl_xor_sync(0xffffffffu, mx, o));
            float ssum = 0.f;
            #pragma unroll
            for (int j = 0; j < 11; j++) { sc[qi][j] = __expf(sc[qi][j] - mx); ssum += sc[qi][j]; }
            #pragma unroll
            for (int o = 16; o; o >>= 1) ssum += __shfl_xor_sync(0xffffffffu, ssum, o);
            float rinv = 1.f / ssum;
            float* arow = g_attn + ((size_t)win*WN + q)*WN;
            #pragma unroll
            for (int j = 0; j < 11; j++) {
                int m = lane + 32*j;
                if (m < WN) arow[m] = sc[qi][j] * rinv;
            }
        }
        __syncwarp();
    }
}

// -------------------- attention: P @ V (packed over m-pairs) -----------------
__global__ __launch_bounds__(512)
void k_att2(const float* __restrict__ V) {
    extern __shared__ float sm[];
    float* vs = sm;                   // 352*100 (rows 343..351 zeroed)
    float* ps = sm + 352*100;         // 16 warps * 8*32
    float* st = ps + 16*256;          // 16 warps * 96*9
    int win = blockIdx.x;
    int tid = threadIdx.x, lane = tid & 31, wp = tid >> 5;
    const float* vw = V + (size_t)win * WN * CDIM;
    for (int e = tid; e < WN * CDIM; e += 512)
        vs[(e / 96) * 100 + (e % 96)] = vw[e];
    for (int e = tid; e < 9*100; e += 512)
        vs[343*100 + e] = 0.f;
    __syncthreads();

    float* myp  = ps + wp * 256;
    float* myst = st + wp * 864;
    float* ob   = g_ot + (size_t)win * WN * CDIM;

    for (int g = wp; g < 43; g += 16) {
        int q0 = g * 8;
        u64 acc2[8][3];
        #pragma unroll
        for (int qi = 0; qi < 8; qi++)
            #pragma unroll
            for (int s = 0; s < 3; s++) acc2[qi][s] = 0ull;

        for (int m0 = 0; m0 < WN; m0 += 32) {
            int mlen = WN - m0; if (mlen > 32) mlen = 32;
            #pragma unroll
            for (int qi = 0; qi < 8; qi++) {
                int q = q0 + qi;
                myp[qi*32 + lane] =
                    (q < WN && lane < mlen) ? g_attn[((size_t)win*WN + q)*WN + m0 + lane] : 0.f;
            }
            __syncwarp();
            #pragma unroll 4
            for (int mi = 0; mi < 32; mi += 2) {
                int m = m0 + mi;
                u64 v0 = pack2(vs[m*100 + lane],      vs[(m+1)*100 + lane]);
                u64 v1 = pack2(vs[m*100 + lane + 32], vs[(m+1)*100 + lane + 32]);
                u64 v2 = pack2(vs[m*100 + lane + 64], vs[(m+1)*100 + lane + 64]);
                #pragma unroll
                for (int qi = 0; qi < 8; qi++) {
                    u64 pp = *(const u64*)(myp + qi*32 + mi);
                    acc2[qi][0] = ffma2(pp, v0, acc2[qi][0]);
                    acc2[qi][1] = ffma2(pp, v1, acc2[qi][1]);
                    acc2[qi][2] = ffma2(pp, v2, acc2[qi][2]);
                }
            }
            __syncwarp();
        }
        #pragma unroll
        for (int qi = 0; qi < 8; qi++) {
            myst[(lane)     *9 + qi] = hadd2(acc2[qi][0]);
            myst[(lane + 32)*9 + qi] = hadd2(acc2[qi][1]);
            myst[(lane + 64)*9 + qi] = hadd2(acc2[qi][2]);
        }
        __syncwarp();
        for (int e = lane; e < 768; e += 32) {
            int c = e >> 3, qq = e & 7;
            int q = q0 + qq;
            if (q < WN) ob[(size_t)c*WN + q] = myst[c*9 + qq];
        }
        __syncwarp();
    }
}

// -------------------- window-reverse + roll(+3) + residual + LN2 (fused) -----
__global__ __launch_bounds__(256)
void k_resln2(const float* __restrict__ x,
              const float* __restrict__ gg, const float* __restrict__ bb) {
    __shared__ float xs[32*101];
    int p0 = blockIdx.x * 32;
    int tid = threadIdx.x, lane = tid & 31, wp = tid >> 5;
    for (int e = tid; e < 96*32; e += 256) {
        int c = e >> 5, i = e & 31;
        xs[i*101 + c] = x[(size_t)c*NTOK + p0 + i];
    }
    __syncthreads();
    #pragma unroll
    for (int ii = wp; ii < 32; ii += 8) {
        int p = p0 + ii;
        int s = p / 3136, r = p % 3136, h = r / 56, w = r % 56;
        int s2 = (s >= 3) ? s - 3 : s + 53;
        int h2 = (h >= 3) ? h - 3 : h + 53;
        int w2 = (w >= 3) ? w - 3 : w + 53;
        int win = (s2/7)*64 + (h2/7)*8 + (w2/7);
        int np  = (s2%7)*49 + (h2%7)*7 + (w2%7);
        const float* ov = g_ot + (size_t)win*WN*CDIM + np*96;
        float v0 = xs[ii*101 + lane]      + ov[lane];
        float v1 = xs[ii*101 + lane + 32] + ov[lane + 32];
        float v2 = xs[ii*101 + lane + 64] + ov[lane + 64];
        float* xr = g_xres + (size_t)p*CDIM;
        xr[lane] = v0; xr[lane + 32] = v1; xr[lane + 64] = v2;
        float sum = v0 + v1 + v2, sq = v0*v0 + v1*v1 + v2*v2;
        #pragma unroll
        for (int o = 16; o; o >>= 1) {
            sum += __shfl_xor_sync(0xffffffffu, sum, o);
            sq  += __shfl_xor_sync(0xffffffffu, sq, o);
        }
        float mean = sum * (1.f/96.f);
        float var  = sq * (1.f/96.f) - mean*mean;
        float inv  = rsqrtf(var + 1e-5f);
        float* yo = g_ln2 + (size_t)p*CDIM;
        yo[lane]      = (v0 - mean)*inv*gg[lane]      + bb[lane];
        yo[lane + 32] = (v1 - mean)*inv*gg[lane + 32] + bb[lane + 32];
        yo[lane + 64] = (v2 - mean)*inv*gg[lane + 64] + bb[lane + 64];
    }
}

// -------------------- launch --------------------------------------------------
extern "C" void kernel_launch(void* const* d_in, const int* in_sizes, int n_in,
                              void* d_out, int out_size) {
    const float* x   = (const float*)d_in[0];
    const float* n1g = (const float*)d_in[1];
    const float* n1b = (const float*)d_in[2];
    const float* wq  = (const float*)d_in[3];
    const float* bq  = (const float*)d_in[4];
    const float* wk  = (const float*)d_in[5];
    const float* bk  = (const float*)d_in[6];
    const float* wv  = (const float*)d_in[7];
    const float* bv  = (const float*)d_in[8];
    const float* dqw = (const float*)d_in[9];
    const float* dqb = (const float*)d_in[10];
    const float* dkw = (const float*)d_in[11];
    const float* dkb = (const float*)d_in[12];
    const float* dvw = (const float*)d_in[13];
    const float* dvb = (const float*)d_in[14];
    const float* n2g = (const float*)d_in[15];
    const float* n2b = (const float*)d_in[16];
    const float* f1w = (const float*)d_in[17];
    const float* f1b = (const float*)d_in[18];
    const float* f2w = (const float*)d_in[19];
    const float* f2b = (const float*)d_in[20];
    float* out = (float*)d_out;

    float *pxw, *pqp, *pkp, *pvp, *pq, *pk, *pv, *pln2, *ph, *pxres, *pwqkv, *pbqkv;
    cudaGetSymbolAddress((void**)&pxw,   g_xw);
    cudaGetSymbolAddress((void**)&pqp,   g_qp);
    cudaGetSymbolAddress((void**)&pkp,   g_kp);
    cudaGetSymbolAddress((void**)&pvp,   g_vp);
    cudaGetSymbolAddress((void**)&pq,    g_q);
    cudaGetSymbolAddress((void**)&pk,    g_k);
    cudaGetSymbolAddress((void**)&pv,    g_v);
    cudaGetSymbolAddress((void**)&pln2,  g_ln2);
    cudaGetSymbolAddress((void**)&ph,    g_h);
    cudaGetSymbolAddress((void**)&pxres, g_xres);
    cudaGetSymbolAddress((void**)&pwqkv, g_wqkv);
    cudaGetSymbolAddress((void**)&pbqkv, g_bqkv);

    const int ATT1_SMEM = (352*100 + 12*384) * 4;
    const int ATT2_SMEM = (352*100 + 16*256 + 16*864) * 4;
    cudaFuncSetAttribute(k_att1, cudaFuncAttributeMaxDynamicSharedMemorySize, ATT1_SMEM);
    cudaFuncSetAttribute(k_att2, cudaFuncAttributeMaxDynamicSharedMemorySize, ATT2_SMEM);

    k_prep<<<(3*CDIM*CDIM + 255)/256, 256>>>(wq, bq, wk, bk, wv, bv);
    k_ln1<<<NTOK/64, 256>>>(x, n1g, n1b);

    dim3 gq(NTOK/128, 3);
    k_gemm<3><<<gq, 256>>>(pxw, pwqkv, pbqkv, NTOK, 288, 96, pqp, pkp, pvp, nullptr, nullptr);

    dim3 gdw(NW, 3);
    k_dw<<<gdw, 392>>>(pqp, dqw, dqb, pq);
    k_dw<<<gdw, 392>>>(pkp, dkw, dkb, pk);
    k_dw<<<gdw, 392>>>(pvp, dvw, dvb, pv);

    k_att1<<<NW, 384, ATT1_SMEM>>>(pq, pk);
    k_att2<<<NW, 512, ATT2_SMEM>>>(pv);

    k_resln2<<<NTOK/32, 256>>>(x, n2g, n2b);

    dim3 g2(NTOK/128, HIDD/96);
    k_gemm<1><<<g2, 256>>>(pln2, f1w, f1b, NTOK, HIDD, 96, ph, nullptr, nullptr, nullptr, nullptr);
    dim3 g3(NTOK/128, 1);
    k_gemm<2><<<g3, 256>>>(ph, f2w, f2b, NTOK, 96, HIDD, nullptr, nullptr, nullptr, pxres, out);
}